// round 2
// baseline (speedup 1.0000x reference)
#include <cuda_runtime.h>
#include <math.h>

#define BATCH 2
#define NPTS  4096
#define MQ    4096

// scratch for per-scale pooled features [B*M][128]
__device__ float g_f1[BATCH * MQ * 128];
__device__ float g_f2[BATCH * MQ * 128];

struct __align__(16) Smem {
    float Wt3[64 * 129];     // transposed layer-3 weights [k][o], stride 129 (conflict-free)
    float relx[64], rely[64], relz[64], wgt[64], pzs[64], la[64], lb[64];
    float h1buf[4 * 4 * 32]; // [warp][n][lane]
    float h2buf[4 * 4 * 64]; // [warp][n][chan]
    float fblk[128];
    float zv[3], xvv[3], yvv[3];
    float q[3];
    int   nidx[64];
    int   wcnt[4];
    int   cnt;
};

__device__ __forceinline__ float f4c(const float4& v, int c) {
    switch (c) { case 0: return v.x; case 1: return v.y; case 2: return v.z; default: return v.w; }
}

// SCALE: 0 -> write g_f1, 1 -> write g_f2
template <int NS, int SCALE>
__global__ void __launch_bounds__(128)
scale_kernel(const float* __restrict__ pts,
             const float* __restrict__ W1, const float* __restrict__ G1, const float* __restrict__ B1,
             const float* __restrict__ W2, const float* __restrict__ G2, const float* __restrict__ B2,
             const float* __restrict__ W3L, const float* __restrict__ G3, const float* __restrict__ B3,
             float radius)
{
    __shared__ Smem s;
    const int tid  = threadIdx.x;
    const int lane = tid & 31;
    const int wid  = tid >> 5;
    const int pm   = blockIdx.x;
    const int b    = pm / MQ;
    const int m    = pm - b * MQ;
    const float* base = pts + (size_t)b * NPTS * 3;
    float* fout = (SCALE == 0) ? g_f1 : g_f2;

    // stage transposed layer-3 weights (overlaps with ball query latency)
    for (int i = tid; i < 128 * 64; i += 128) {
        int o = i >> 6, k = i & 63;
        s.Wt3[k * 129 + o] = W3L[i];
    }

    if (tid == 0) {
        s.cnt = 0;
        s.q[0] = base[m * 3 + 0];
        s.q[1] = base[m * 3 + 1];
        s.q[2] = base[m * 3 + 2];
    }
    __syncthreads();
    const float qx = s.q[0], qy = s.q[1], qz = s.q[2];
    const float r2 = radius * radius;

    // ---------------- ball query: first NS indices (ascending) inside radius ----------------
    for (int chunk = 0; chunk < NPTS; chunk += 128) {
        int p = chunk + tid;                       // NPTS % 128 == 0
        float dx = base[p * 3 + 0] - qx;
        float dy = base[p * 3 + 1] - qy;
        float dz = base[p * 3 + 2] - qz;
        bool pred = (dx * dx + dy * dy + dz * dz) < r2;
        unsigned bal = __ballot_sync(0xffffffffu, pred);
        if (lane == 0) s.wcnt[wid] = __popc(bal);
        __syncthreads();
        int off = s.cnt;
        #pragma unroll
        for (int w = 0; w < 4; w++) if (w < wid) off += s.wcnt[w];
        int pos = off + __popc(bal & ((1u << lane) - 1u));
        if (pred && pos < NS) s.nidx[pos] = p;
        __syncthreads();
        if (tid == 0) s.cnt += s.wcnt[0] + s.wcnt[1] + s.wcnt[2] + s.wcnt[3];
        __syncthreads();
        if (s.cnt >= NS) break;
    }
    int cnt = min(s.cnt, NS);                      // cnt >= 1 (self point is in its own ball)
    if (tid >= cnt && tid < NS) s.nidx[tid] = s.nidx[0];   // replicate first neighbor
    __syncthreads();

    // ---------------- relative coords + weights ----------------
    if (tid < NS) {
        int idx = s.nidx[tid];
        float rx = base[idx * 3 + 0] - qx;
        float ry = base[idx * 3 + 1] - qy;
        float rz = base[idx * 3 + 2] - qz;
        float d  = sqrtf(rx * rx + ry * ry + rz * rz);
        s.relx[tid] = rx; s.rely[tid] = ry; s.relz[tid] = rz;
        s.wgt[tid]  = fmaxf(radius - d, 0.0f);
    }
    __syncthreads();

    // ---------------- weighted covariance + Σrel (warp 0, fp64) ----------------
    if (tid < 32) {
        double acc[10];
        #pragma unroll
        for (int i = 0; i < 10; i++) acc[i] = 0.0;
        for (int si = tid; si < NS; si += 32) {
            double rx = s.relx[si], ry = s.rely[si], rz = s.relz[si], w = s.wgt[si];
            acc[0] += w * rx * rx; acc[1] += w * rx * ry; acc[2] += w * rx * rz;
            acc[3] += w * ry * ry; acc[4] += w * ry * rz; acc[5] += w * rz * rz;
            acc[6] += w; acc[7] += rx; acc[8] += ry; acc[9] += rz;
        }
        #pragma unroll
        for (int off = 16; off; off >>= 1) {
            #pragma unroll
            for (int i = 0; i < 10; i++) acc[i] += __shfl_down_sync(0xffffffffu, acc[i], off);
        }
        if (tid == 0) {
            double inv = 1.0 / (acc[6] + 1e-8);
            double a00 = acc[0] * inv, a01 = acc[1] * inv, a02 = acc[2] * inv;
            double a11 = acc[3] * inv, a12 = acc[4] * inv, a22 = acc[5] * inv;
            double zx, zy, zz;
            double p1 = a01 * a01 + a02 * a02 + a12 * a12;
            if (p1 < 1e-30) {
                // (near-)diagonal: axis of smallest diagonal entry
                if (a00 <= a11 && a00 <= a22)      { zx = 1; zy = 0; zz = 0; }
                else if (a11 <= a22)               { zx = 0; zy = 1; zz = 0; }
                else                               { zx = 0; zy = 0; zz = 1; }
            } else {
                double q  = (a00 + a11 + a22) / 3.0;
                double b00 = a00 - q, b11 = a11 - q, b22 = a22 - q;
                double p2 = b00 * b00 + b11 * b11 + b22 * b22 + 2.0 * p1;
                double p  = sqrt(p2 / 6.0);
                double ip = 1.0 / p;
                double c00 = b00 * ip, c01 = a01 * ip, c02 = a02 * ip;
                double c11 = b11 * ip, c12 = a12 * ip, c22 = b22 * ip;
                double detB = c00 * (c11 * c22 - c12 * c12)
                            - c01 * (c01 * c22 - c12 * c02)
                            + c02 * (c01 * c12 - c11 * c02);
                double r = 0.5 * detB;
                r = fmin(1.0, fmax(-1.0, r));
                double phi = acos(r) / 3.0;
                double lmin = q + 2.0 * p * cos(phi + 2.0943951023931953); // + 2π/3
                // eigenvector: largest cross product of rows of (A - λI)
                double r0x = a00 - lmin, r0y = a01,        r0z = a02;
                double r1x = a01,        r1y = a11 - lmin, r1z = a12;
                double r2x = a02,        r2y = a12,        r2z = a22 - lmin;
                double v0x = r0y * r1z - r0z * r1y, v0y = r0z * r1x - r0x * r1z, v0z = r0x * r1y - r0y * r1x;
                double v1x = r0y * r2z - r0z * r2y, v1y = r0z * r2x - r0x * r2z, v1z = r0x * r2y - r0y * r2x;
                double v2x = r1y * r2z - r1z * r2y, v2y = r1z * r2x - r1x * r2z, v2z = r1x * r2y - r1y * r2x;
                double n0 = v0x * v0x + v0y * v0y + v0z * v0z;
                double n1 = v1x * v1x + v1y * v1y + v1z * v1z;
                double n2 = v2x * v2x + v2y * v2y + v2z * v2z;
                double vx, vy, vz, nn;
                if (n0 >= n1 && n0 >= n2)      { vx = v0x; vy = v0y; vz = v0z; nn = n0; }
                else if (n1 >= n2)             { vx = v1x; vy = v1y; vz = v1z; nn = n1; }
                else                           { vx = v2x; vy = v2y; vz = v2z; nn = n2; }
                double inr = (nn > 0.0) ? (1.0 / sqrt(nn)) : 0.0;
                zx = vx * inr; zy = vy * inr; zz = vz * inr;
            }
            // sign disambiguation: z away from neighbor mass
            double dotz = acc[7] * zx + acc[8] * zy + acc[9] * zz;
            if (dotz > 0.0) { zx = -zx; zy = -zy; zz = -zz; }
            s.zv[0] = (float)zx; s.zv[1] = (float)zy; s.zv[2] = (float)zz;
        }
    }
    __syncthreads();

    // pz per neighbor
    {
        float zx = s.zv[0], zy = s.zv[1], zz = s.zv[2];
        if (tid < NS)
            s.pzs[tid] = s.relx[tid] * zx + s.rely[tid] * zy + s.relz[tid] * zz;
    }
    __syncthreads();

    // xv accumulation (warp 0, fp64)
    if (tid < 32) {
        double zx = s.zv[0], zy = s.zv[1], zz = s.zv[2];
        double sx = 0, sy = 0, sz = 0;
        for (int si = tid; si < NS; si += 32) {
            double pz = s.pzs[si], w = s.wgt[si];
            double t = (w * w) * (pz * pz);
            sx += t * (s.relx[si] - pz * zx);
            sy += t * (s.rely[si] - pz * zy);
            sz += t * (s.relz[si] - pz * zz);
        }
        #pragma unroll
        for (int off = 16; off; off >>= 1) {
            sx += __shfl_down_sync(0xffffffffu, sx, off);
            sy += __shfl_down_sync(0xffffffffu, sy, off);
            sz += __shfl_down_sync(0xffffffffu, sz, off);
        }
        if (tid == 0) {
            double nrm = sqrt(sx * sx + sy * sy + sz * sz);
            double inr = 1.0 / (nrm + 1e-8);
            float xx = (float)(sx * inr), xy = (float)(sy * inr), xz = (float)(sz * inr);
            s.xvv[0] = xx; s.xvv[1] = xy; s.xvv[2] = xz;
            float zx2 = s.zv[0], zy2 = s.zv[1], zz2 = s.zv[2];
            s.yvv[0] = zy2 * xz - zz2 * xy;
            s.yvv[1] = zz2 * xx - zx2 * xz;
            s.yvv[2] = zx2 * xy - zy2 * xx;
        }
    }
    __syncthreads();

    // LRF coordinates per neighbor: (rel·xv, rel·yv, pz)
    if (tid < NS) {
        float rx = s.relx[tid], ry = s.rely[tid], rz = s.relz[tid];
        s.la[tid] = rx * s.xvv[0] + ry * s.xvv[1] + rz * s.xvv[2];
        s.lb[tid] = rx * s.yvv[0] + ry * s.yvv[1] + rz * s.yvv[2];
    }
    __syncthreads();

    // ---------------- MLP 3->32->64->128 (+BN+ReLU) + max over neighbors ----------------
    const float bns = 0.99999500003749968752f;  // 1/sqrt(1+1e-5)
    float wa0 = W1[lane * 3 + 0], wa1 = W1[lane * 3 + 1], wa2 = W1[lane * 3 + 2];
    float s1r = G1[lane] * bns, b1r = B1[lane];
    float4 w2ra[8], w2rb[8];
    const float4* W2v = (const float4*)W2;
    #pragma unroll
    for (int t = 0; t < 8; t++) { w2ra[t] = W2v[lane * 8 + t]; w2rb[t] = W2v[(lane + 32) * 8 + t]; }
    float s2ra = G2[lane] * bns, b2ra = B2[lane];
    float s2rb = G2[lane + 32] * bns, b2rb = B2[lane + 32];
    float s3r[4], b3r[4];
    #pragma unroll
    for (int j = 0; j < 4; j++) { s3r[j] = G3[lane + 32 * j] * bns; b3r[j] = B3[lane + 32 * j]; }

    const int CH = NS / 4;                 // neighbors per warp
    float fm0 = 0.f, fm1 = 0.f, fm2 = 0.f, fm3 = 0.f;   // ReLU outputs >= 0

    for (int s0 = wid * CH; s0 < wid * CH + CH; s0 += 4) {
        // layer 1
        #pragma unroll
        for (int n = 0; n < 4; n++) {
            float a = s.la[s0 + n], bq = s.lb[s0 + n], c = s.pzs[s0 + n];
            float v = fmaf(wa0, a, fmaf(wa1, bq, wa2 * c));
            v = fmaxf(fmaf(v, s1r, b1r), 0.f);
            s.h1buf[wid * 128 + n * 32 + lane] = v;
        }
        __syncwarp();
        // layer 2 (weights in registers)
        float h2a[4] = {0, 0, 0, 0}, h2b[4] = {0, 0, 0, 0};
        #pragma unroll
        for (int k = 0; k < 32; k++) {
            float wA = f4c(w2ra[k >> 2], k & 3);
            float wB = f4c(w2rb[k >> 2], k & 3);
            #pragma unroll
            for (int n = 0; n < 4; n++) {
                float h = s.h1buf[wid * 128 + n * 32 + k];
                h2a[n] = fmaf(wA, h, h2a[n]);
                h2b[n] = fmaf(wB, h, h2b[n]);
            }
        }
        #pragma unroll
        for (int n = 0; n < 4; n++) {
            s.h2buf[wid * 256 + n * 64 + lane]      = fmaxf(fmaf(h2a[n], s2ra, b2ra), 0.f);
            s.h2buf[wid * 256 + n * 64 + lane + 32] = fmaxf(fmaf(h2b[n], s2rb, b2rb), 0.f);
        }
        __syncwarp();
        // layer 3 (weights in shared, neighbor-blocked)
        float a30[4] = {0, 0, 0, 0}, a31[4] = {0, 0, 0, 0}, a32[4] = {0, 0, 0, 0}, a33[4] = {0, 0, 0, 0};
        #pragma unroll
        for (int k = 0; k < 64; k++) {
            float w0 = s.Wt3[k * 129 + lane];
            float w1v = s.Wt3[k * 129 + lane + 32];
            float w2v = s.Wt3[k * 129 + lane + 64];
            float w3v = s.Wt3[k * 129 + lane + 96];
            #pragma unroll
            for (int n = 0; n < 4; n++) {
                float h = s.h2buf[wid * 256 + n * 64 + k];
                a30[n] = fmaf(w0, h, a30[n]);
                a31[n] = fmaf(w1v, h, a31[n]);
                a32[n] = fmaf(w2v, h, a32[n]);
                a33[n] = fmaf(w3v, h, a33[n]);
            }
        }
        #pragma unroll
        for (int n = 0; n < 4; n++) {
            fm0 = fmaxf(fm0, fmaxf(fmaf(a30[n], s3r[0], b3r[0]), 0.f));
            fm1 = fmaxf(fm1, fmaxf(fmaf(a31[n], s3r[1], b3r[1]), 0.f));
            fm2 = fmaxf(fm2, fmaxf(fmaf(a32[n], s3r[2], b3r[2]), 0.f));
            fm3 = fmaxf(fm3, fmaxf(fmaf(a33[n], s3r[3], b3r[3]), 0.f));
        }
        __syncwarp();
    }

    // cross-warp max
    if (wid == 0) {
        s.fblk[lane] = fm0; s.fblk[lane + 32] = fm1; s.fblk[lane + 64] = fm2; s.fblk[lane + 96] = fm3;
    }
    __syncthreads();
    #pragma unroll
    for (int w = 1; w < 4; w++) {
        if (wid == w) {
            s.fblk[lane]      = fmaxf(s.fblk[lane], fm0);
            s.fblk[lane + 32] = fmaxf(s.fblk[lane + 32], fm1);
            s.fblk[lane + 64] = fmaxf(s.fblk[lane + 64], fm2);
            s.fblk[lane + 96] = fmaxf(s.fblk[lane + 96], fm3);
        }
        __syncthreads();
    }
    fout[(size_t)pm * 128 + tid] = s.fblk[tid];
}

// ---------------- final linear: out[b,m,o] = sum_c feat[c] * W3[o,c] + b3[o] ----------------
__global__ void __launch_bounds__(128)
final_kernel(const float* __restrict__ W3f, const float* __restrict__ B3f, float* __restrict__ out)
{
    __shared__ float feat[256];
    const int tid = threadIdx.x, lane = tid & 31, wid = tid >> 5;
    const int pm = blockIdx.x;
    feat[tid]       = g_f1[(size_t)pm * 128 + tid];
    feat[tid + 128] = g_f2[(size_t)pm * 128 + tid];
    __syncthreads();
    for (int oo = 0; oo < 32; oo++) {
        int o = wid * 32 + oo;
        const float* row = W3f + (size_t)o * 256;
        float acc = 0.f;
        #pragma unroll
        for (int t = 0; t < 8; t++)
            acc = fmaf(row[t * 32 + lane], feat[t * 32 + lane], acc);
        #pragma unroll
        for (int off = 16; off; off >>= 1)
            acc += __shfl_down_sync(0xffffffffu, acc, off);
        if (lane == 0) out[(size_t)pm * 128 + o] = acc + B3f[o];
    }
}

extern "C" void kernel_launch(void* const* d_in, const int* in_sizes, int n_in,
                              void* d_out, int out_size)
{
    const float* pts  = (const float*)d_in[0];
    const float* w1a  = (const float*)d_in[1];
    const float* g1a  = (const float*)d_in[2];
    const float* bb1a = (const float*)d_in[3];
    const float* w1b  = (const float*)d_in[4];
    const float* g1b  = (const float*)d_in[5];
    const float* bb1b = (const float*)d_in[6];
    const float* w1c  = (const float*)d_in[7];
    const float* g1c  = (const float*)d_in[8];
    const float* bb1c = (const float*)d_in[9];
    const float* w2a  = (const float*)d_in[10];
    const float* g2a  = (const float*)d_in[11];
    const float* bb2a = (const float*)d_in[12];
    const float* w2b  = (const float*)d_in[13];
    const float* g2b  = (const float*)d_in[14];
    const float* bb2b = (const float*)d_in[15];
    const float* w2c  = (const float*)d_in[16];
    const float* g2c  = (const float*)d_in[17];
    const float* bb2c = (const float*)d_in[18];
    const float* w3   = (const float*)d_in[19];
    const float* b3   = (const float*)d_in[20];

    const int nblocks = BATCH * MQ;
    scale_kernel<32, 0><<<nblocks, 128>>>(pts, w1a, g1a, bb1a, w1b, g1b, bb1b,
                                          w1c, g1c, bb1c, 0.1f);
    scale_kernel<64, 1><<<nblocks, 128>>>(pts, w2a, g2a, bb2a, w2b, g2b, bb2b,
                                          w2c, g2c, bb2c, 0.2f);
    final_kernel<<<nblocks, 128>>>(w3, b3, (float*)d_out);
}

// round 4
// speedup vs baseline: 1.3392x; 1.3392x over previous
#include <cuda_runtime.h>
#include <math.h>

#define BATCH 2
#define NPTS  4096
#define MQ    4096
#define NQ    (BATCH * MQ)

// scratch
__device__ float g_f1[NQ * 128];
__device__ float g_f2[NQ * 128];
__device__ float g_sx[BATCH * NPTS], g_sy[BATCH * NPTS], g_sz[BATCH * NPTS];
__device__ float g_W3t[256 * 128];   // transposed final weights [c][o]

// ---------------- f32x2 helpers ----------------
typedef unsigned long long u64;
__device__ __forceinline__ u64 pack2(float x) {
    u64 r; asm("mov.b64 %0, {%1,%1};" : "=l"(r) : "f"(x)); return r;
}
__device__ __forceinline__ u64 pack2(float x, float y) {
    u64 r; asm("mov.b64 %0, {%1,%2};" : "=l"(r) : "f"(x), "f"(y)); return r;
}
__device__ __forceinline__ void unpack2(u64 v, float& x, float& y) {
    asm("mov.b64 {%0,%1}, %2;" : "=f"(x), "=f"(y) : "l"(v));
}
__device__ __forceinline__ void ffma2(u64& d, u64 a, u64 b) {
    asm("fma.rn.f32x2 %0, %1, %2, %0;" : "+l"(d) : "l"(a), "l"(b));
}
__device__ __forceinline__ u64 ffma2c(u64 a, u64 b, u64 c) {
    u64 d; asm("fma.rn.f32x2 %0, %1, %2, %3;" : "=l"(d) : "l"(a), "l"(b), "l"(c)); return d;
}

// ---------------- shared memory layout (dynamic, scale kernels) ----------------
// Wt3s  : float [64][128]            32768 B   @ 0
// W2p   : u64   [32][64] dup-packed  16384 B   @ 32768
// h1p   : u64   [8 warps][32*5]      10240 B   @ 49152
// h2p   : u64   [8 warps][64*5]      20480 B   @ 59392
// warp scratch: 8 warps * 464 floats 14848 B   @ 79872
#define SMEM_TOTAL 94720
#define FINAL_SMEM (32 * 256 * 4 + 64 * 128 * 4)   // 65536

template <int NS, int SCALE>
__global__ void __launch_bounds__(256, 2)
scale_kernel(const float* __restrict__ pts,
             const float* __restrict__ W1, const float* __restrict__ G1, const float* __restrict__ B1,
             const float* __restrict__ W2, const float* __restrict__ G2, const float* __restrict__ B2,
             const float* __restrict__ W3L, const float* __restrict__ G3, const float* __restrict__ B3,
             float radius)
{
    extern __shared__ unsigned char smraw[];
    float* Wt3s = (float*)smraw;
    u64*   W2p  = (u64*)(smraw + 32768);
    const int tid  = threadIdx.x;
    const int lane = tid & 31;
    const int wid  = tid >> 5;
    u64*   h1p  = (u64*)(smraw + 49152) + wid * 160;
    u64*   h2p  = (u64*)(smraw + 59392) + wid * 320;
    float* wr   = (float*)(smraw + 79872) + wid * 464;
    float* relx = wr;        float* rely = wr + 64;  float* relz = wr + 128;
    float* wgt  = wr + 192;  float* pzv  = wr + 256; float* la   = wr + 320;
    float* lb   = wr + 384;  float* msc  = wr + 448;

    // ---- stage weights (no sync yet; sync happens before MLP) ----
    for (int i = tid; i < 128 * 64; i += 256) {
        int o = i >> 6, k = i & 63;
        Wt3s[k * 128 + o] = W3L[i];
    }
    for (int i = tid; i < 64 * 32; i += 256) {
        int ch = i >> 5, k = i & 31;
        W2p[k * 64 + ch] = pack2(W2[i]);
    }

    const int qi = blockIdx.x * 8 + wid;       // query index 0..8191
    const int b  = qi >> 12;
    const int m  = qi & (MQ - 1);
    const float* px = g_sx + b * NPTS;
    const float* py = g_sy + b * NPTS;
    const float* pz = g_sz + b * NPTS;
    const float qx = px[m], qy = py[m], qz = pz[m];
    const float r2 = radius * radius;
    const unsigned lmask = (1u << lane) - 1u;

    // ---------------- warp-synchronous ball query ----------------
    int cnt = 0;
    for (int c = 0; c < NPTS && cnt < NS; c += 32) {
        int p = c + lane;
        float dx = px[p] - qx, dy = py[p] - qy, dz = pz[p] - qz;
        float d2 = dx * dx + dy * dy + dz * dz;
        bool pred = d2 < r2;
        unsigned bal = __ballot_sync(0xffffffffu, pred);
        int pos = cnt + __popc(bal & lmask);
        if (pred && pos < NS) {
            relx[pos] = dx; rely[pos] = dy; relz[pos] = dz;
            wgt[pos]  = fmaxf(radius - sqrtf(d2), 0.0f);
        }
        cnt += __popc(bal);
    }
    cnt = min(cnt, NS);
    __syncwarp();
    {   // replicate first neighbor into unfilled slots
        float r0x = relx[0], r0y = rely[0], r0z = relz[0], w0 = wgt[0];
        for (int i = cnt + lane; i < NS; i += 32) {
            relx[i] = r0x; rely[i] = r0y; relz[i] = r0z; wgt[i] = w0;
        }
    }
    __syncwarp();

    // ---------------- weighted covariance + Σrel (fp64 warp reduce) ----------------
    {
        double acc[10];
        #pragma unroll
        for (int i = 0; i < 10; i++) acc[i] = 0.0;
        #pragma unroll
        for (int si = lane; si < NS; si += 32) {
            double rx = relx[si], ry = rely[si], rz = relz[si], w = wgt[si];
            acc[0] += w * rx * rx; acc[1] += w * rx * ry; acc[2] += w * rx * rz;
            acc[3] += w * ry * ry; acc[4] += w * ry * rz; acc[5] += w * rz * rz;
            acc[6] += w; acc[7] += rx; acc[8] += ry; acc[9] += rz;
        }
        #pragma unroll
        for (int off = 16; off; off >>= 1) {
            #pragma unroll
            for (int i = 0; i < 10; i++) acc[i] += __shfl_down_sync(0xffffffffu, acc[i], off);
        }
        if (lane == 0) {
            double inv = 1.0 / (acc[6] + 1e-8);
            double a00 = acc[0] * inv, a01 = acc[1] * inv, a02 = acc[2] * inv;
            double a11 = acc[3] * inv, a12 = acc[4] * inv, a22 = acc[5] * inv;
            double zx, zy, zz;
            double p1 = a01 * a01 + a02 * a02 + a12 * a12;
            if (p1 < 1e-30) {
                if (a00 <= a11 && a00 <= a22)      { zx = 1; zy = 0; zz = 0; }
                else if (a11 <= a22)               { zx = 0; zy = 1; zz = 0; }
                else                               { zx = 0; zy = 0; zz = 1; }
            } else {
                double q  = (a00 + a11 + a22) / 3.0;
                double b00 = a00 - q, b11 = a11 - q, b22 = a22 - q;
                double p2 = b00 * b00 + b11 * b11 + b22 * b22 + 2.0 * p1;
                double p  = sqrt(p2 / 6.0);
                double ip = 1.0 / p;
                double c00 = b00 * ip, c01 = a01 * ip, c02 = a02 * ip;
                double c11 = b11 * ip, c12 = a12 * ip, c22 = b22 * ip;
                double detB = c00 * (c11 * c22 - c12 * c12)
                            - c01 * (c01 * c22 - c12 * c02)
                            + c02 * (c01 * c12 - c11 * c02);
                double r = fmin(1.0, fmax(-1.0, 0.5 * detB));
                double phi = acos(r) / 3.0;
                double lmin = q + 2.0 * p * cos(phi + 2.0943951023931953);
                double r0x = a00 - lmin, r0y = a01,        r0z = a02;
                double r1x = a01,        r1y = a11 - lmin, r1z = a12;
                double r2x = a02,        r2y = a12,        r2z = a22 - lmin;
                double v0x = r0y * r1z - r0z * r1y, v0y = r0z * r1x - r0x * r1z, v0z = r0x * r1y - r0y * r1x;
                double v1x = r0y * r2z - r0z * r2y, v1y = r0z * r2x - r0x * r2z, v1z = r0x * r2y - r0y * r2x;
                double v2x = r1y * r2z - r1z * r2y, v2y = r1z * r2x - r1x * r2z, v2z = r1x * r2y - r1y * r2x;
                double n0 = v0x * v0x + v0y * v0y + v0z * v0z;
                double n1 = v1x * v1x + v1y * v1y + v1z * v1z;
                double n2 = v2x * v2x + v2y * v2y + v2z * v2z;
                double vx, vy, vz, nn;
                if (n0 >= n1 && n0 >= n2)      { vx = v0x; vy = v0y; vz = v0z; nn = n0; }
                else if (n1 >= n2)             { vx = v1x; vy = v1y; vz = v1z; nn = n1; }
                else                           { vx = v2x; vy = v2y; vz = v2z; nn = n2; }
                double inr = (nn > 0.0) ? (1.0 / sqrt(nn)) : 0.0;
                zx = vx * inr; zy = vy * inr; zz = vz * inr;
            }
            double dotz = acc[7] * zx + acc[8] * zy + acc[9] * zz;
            if (dotz > 0.0) { zx = -zx; zy = -zy; zz = -zz; }
            msc[0] = (float)zx; msc[1] = (float)zy; msc[2] = (float)zz;
        }
    }
    __syncwarp();

    {   // pz per neighbor
        float zx = msc[0], zy = msc[1], zz = msc[2];
        #pragma unroll
        for (int i = lane; i < NS; i += 32)
            pzv[i] = relx[i] * zx + rely[i] * zy + relz[i] * zz;
    }
    __syncwarp();

    {   // xv accumulation (fp64 warp reduce)
        double zx = msc[0], zy = msc[1], zz = msc[2];
        double sx = 0, sy = 0, sz = 0;
        #pragma unroll
        for (int si = lane; si < NS; si += 32) {
            double pzd = pzv[si], w = wgt[si];
            double t = (w * w) * (pzd * pzd);
            sx += t * (relx[si] - pzd * zx);
            sy += t * (rely[si] - pzd * zy);
            sz += t * (relz[si] - pzd * zz);
        }
        #pragma unroll
        for (int off = 16; off; off >>= 1) {
            sx += __shfl_down_sync(0xffffffffu, sx, off);
            sy += __shfl_down_sync(0xffffffffu, sy, off);
            sz += __shfl_down_sync(0xffffffffu, sz, off);
        }
        if (lane == 0) {
            double nrm = sqrt(sx * sx + sy * sy + sz * sz);
            double inr = 1.0 / (nrm + 1e-8);
            float xx = (float)(sx * inr), xy = (float)(sy * inr), xz = (float)(sz * inr);
            msc[3] = xx; msc[4] = xy; msc[5] = xz;
            float zx2 = msc[0], zy2 = msc[1], zz2 = msc[2];
            msc[6] = zy2 * xz - zz2 * xy;
            msc[7] = zz2 * xx - zx2 * xz;
            msc[8] = zx2 * xy - zy2 * xx;
        }
    }
    __syncwarp();

    {   // LRF in-plane coordinates
        float xx = msc[3], xy = msc[4], xz = msc[5];
        float yx = msc[6], yy = msc[7], yz = msc[8];
        #pragma unroll
        for (int i = lane; i < NS; i += 32) {
            float rx = relx[i], ry = rely[i], rz = relz[i];
            la[i] = rx * xx + ry * xy + rz * xz;
            lb[i] = rx * yx + ry * yy + rz * yz;
        }
    }

    __syncthreads();   // weights staged + all warps' LRF data in place

    // ---------------- packed MLP 3->32->64->128 + max over neighbors ----------------
    const float bns = 0.99999500003749968752f;  // 1/sqrt(1+1e-5)
    const float wa0 = W1[lane * 3 + 0], wa1 = W1[lane * 3 + 1], wa2 = W1[lane * 3 + 2];
    const float s1  = G1[lane] * bns,  b1v = B1[lane];
    const u64 s2pA = pack2(G2[lane] * bns),        b2pA = pack2(B2[lane]);
    const u64 s2pB = pack2(G2[lane + 32] * bns),   b2pB = pack2(B2[lane + 32]);
    u64 s3p[4], b3p[4];
    #pragma unroll
    for (int j = 0; j < 4; j++) { s3p[j] = pack2(G3[lane + 32 * j] * bns); b3p[j] = pack2(B3[lane + 32 * j]); }

    float fm[4] = {0.f, 0.f, 0.f, 0.f};

    for (int s0 = 0; s0 < NS; s0 += 8) {
        // layer 1: channel = lane, 8 neighbors -> 4 pairs
        #pragma unroll
        for (int p = 0; p < 4; p++) {
            int n0 = s0 + 2 * p;
            float v0 = fmaf(wa0, la[n0],     fmaf(wa1, lb[n0],     wa2 * pzv[n0]));
            float v1 = fmaf(wa0, la[n0 + 1], fmaf(wa1, lb[n0 + 1], wa2 * pzv[n0 + 1]));
            v0 = fmaxf(fmaf(v0, s1, b1v), 0.f);
            v1 = fmaxf(fmaf(v1, s1, b1v), 0.f);
            h1p[lane * 5 + p] = pack2(v0, v1);
        }
        __syncwarp();

        // layer 2: out channels (lane, lane+32), dup-packed weights from shared
        u64 accA[4] = {0, 0, 0, 0}, accB[4] = {0, 0, 0, 0};
        #pragma unroll
        for (int k = 0; k < 32; k++) {
            u64 wA = W2p[k * 64 + lane];
            u64 wB = W2p[k * 64 + lane + 32];
            #pragma unroll
            for (int p = 0; p < 4; p++) {
                u64 h = h1p[k * 5 + p];
                ffma2(accA[p], wA, h);
                ffma2(accB[p], wB, h);
            }
        }
        #pragma unroll
        for (int p = 0; p < 4; p++) {
            u64 t = ffma2c(accA[p], s2pA, b2pA);
            float x, y; unpack2(t, x, y);
            h2p[lane * 5 + p] = pack2(fmaxf(x, 0.f), fmaxf(y, 0.f));
            t = ffma2c(accB[p], s2pB, b2pB);
            unpack2(t, x, y);
            h2p[(lane + 32) * 5 + p] = pack2(fmaxf(x, 0.f), fmaxf(y, 0.f));
        }
        __syncwarp();

        // layer 3: 4 output groups x 4 neighbor pairs
        u64 acc3[16];
        #pragma unroll
        for (int i = 0; i < 16; i++) acc3[i] = 0;
        #pragma unroll 16
        for (int k = 0; k < 64; k++) {
            const float* wrow = Wt3s + k * 128 + lane;
            u64 wp0 = pack2(wrow[0]);
            u64 wp1 = pack2(wrow[32]);
            u64 wp2 = pack2(wrow[64]);
            u64 wp3 = pack2(wrow[96]);
            #pragma unroll
            for (int p = 0; p < 4; p++) {
                u64 h = h2p[k * 5 + p];
                ffma2(acc3[p],      wp0, h);
                ffma2(acc3[4 + p],  wp1, h);
                ffma2(acc3[8 + p],  wp2, h);
                ffma2(acc3[12 + p], wp3, h);
            }
        }
        #pragma unroll
        for (int j = 0; j < 4; j++) {
            #pragma unroll
            for (int p = 0; p < 4; p++) {
                u64 t = ffma2c(acc3[j * 4 + p], s3p[j], b3p[j]);
                float x, y; unpack2(t, x, y);
                fm[j] = fmaxf(fm[j], fmaxf(x, y));   // fm>=0 handles the ReLU clamp
            }
        }
        __syncwarp();
    }

    float* fout = (SCALE == 0) ? g_f1 : g_f2;
    #pragma unroll
    for (int j = 0; j < 4; j++)
        fout[(size_t)qi * 128 + lane + 32 * j] = fm[j];
}

// ---------------- SoA transpose of the point cloud ----------------
__global__ void soa_kernel(const float* __restrict__ pts)
{
    int i = blockIdx.x * blockDim.x + threadIdx.x;
    if (i < BATCH * NPTS) {
        g_sx[i] = pts[i * 3 + 0];
        g_sy[i] = pts[i * 3 + 1];
        g_sz[i] = pts[i * 3 + 2];
    }
}

// ---------------- transpose final weights [o][c] -> [c][o] ----------------
__global__ void w3t_kernel(const float* __restrict__ w3)
{
    int i = blockIdx.x * blockDim.x + threadIdx.x;   // 128*256
    if (i < 128 * 256) {
        int o = i >> 8, c = i & 255;
        g_W3t[c * 128 + o] = w3[i];
    }
}

// ---------------- final linear: tiled, 32 queries/block (dynamic smem) ----------------
__global__ void __launch_bounds__(256)
final_kernel(const float* __restrict__ B3f, float* __restrict__ out)
{
    extern __shared__ float fsm[];
    float* feats = fsm;            // 32 * 256
    float* wt    = fsm + 32 * 256; // 64 * 128
    const int tid = threadIdx.x, lane = tid & 31, wid = tid >> 5;
    const int q0 = blockIdx.x * 32;

    for (int i = tid; i < 32 * 128; i += 256) {
        int q = i >> 7, c = i & 127;
        feats[q * 256 + c]       = g_f1[(size_t)(q0 + q) * 128 + c];
        feats[q * 256 + 128 + c] = g_f2[(size_t)(q0 + q) * 128 + c];
    }

    float acc[4][4];   // [local query][output group]
    #pragma unroll
    for (int ql = 0; ql < 4; ql++)
        #pragma unroll
        for (int j = 0; j < 4; j++) acc[ql][j] = 0.f;

    const int qbase = wid * 4;
    for (int ct = 0; ct < 4; ct++) {
        __syncthreads();
        for (int i = tid; i < 64 * 128; i += 256)
            wt[i] = g_W3t[ct * 64 * 128 + i];
        __syncthreads();
        #pragma unroll 8
        for (int c = 0; c < 64; c++) {
            float w0 = wt[c * 128 + lane];
            float w1 = wt[c * 128 + lane + 32];
            float w2 = wt[c * 128 + lane + 64];
            float w3v = wt[c * 128 + lane + 96];
            #pragma unroll
            for (int ql = 0; ql < 4; ql++) {
                float f = feats[(qbase + ql) * 256 + ct * 64 + c];
                acc[ql][0] = fmaf(w0, f, acc[ql][0]);
                acc[ql][1] = fmaf(w1, f, acc[ql][1]);
                acc[ql][2] = fmaf(w2, f, acc[ql][2]);
                acc[ql][3] = fmaf(w3v, f, acc[ql][3]);
            }
        }
    }
    #pragma unroll
    for (int ql = 0; ql < 4; ql++)
        #pragma unroll
        for (int j = 0; j < 4; j++)
            out[(size_t)(q0 + qbase + ql) * 128 + lane + 32 * j] = acc[ql][j] + B3f[lane + 32 * j];
}

extern "C" void kernel_launch(void* const* d_in, const int* in_sizes, int n_in,
                              void* d_out, int out_size)
{
    const float* pts  = (const float*)d_in[0];
    const float* w1a  = (const float*)d_in[1];
    const float* g1a  = (const float*)d_in[2];
    const float* bb1a = (const float*)d_in[3];
    const float* w1b  = (const float*)d_in[4];
    const float* g1b  = (const float*)d_in[5];
    const float* bb1b = (const float*)d_in[6];
    const float* w1c  = (const float*)d_in[7];
    const float* g1c  = (const float*)d_in[8];
    const float* bb1c = (const float*)d_in[9];
    const float* w2a  = (const float*)d_in[10];
    const float* g2a  = (const float*)d_in[11];
    const float* bb2a = (const float*)d_in[12];
    const float* w2b  = (const float*)d_in[13];
    const float* g2b  = (const float*)d_in[14];
    const float* bb2b = (const float*)d_in[15];
    const float* w2c  = (const float*)d_in[16];
    const float* g2c  = (const float*)d_in[17];
    const float* bb2c = (const float*)d_in[18];
    const float* w3   = (const float*)d_in[19];
    const float* b3   = (const float*)d_in[20];

    cudaFuncSetAttribute(scale_kernel<32, 0>, cudaFuncAttributeMaxDynamicSharedMemorySize, SMEM_TOTAL);
    cudaFuncSetAttribute(scale_kernel<64, 1>, cudaFuncAttributeMaxDynamicSharedMemorySize, SMEM_TOTAL);
    cudaFuncSetAttribute(final_kernel, cudaFuncAttributeMaxDynamicSharedMemorySize, FINAL_SMEM);

    soa_kernel<<<(BATCH * NPTS + 255) / 256, 256>>>(pts);
    w3t_kernel<<<(128 * 256 + 255) / 256, 256>>>(w3);
    scale_kernel<32, 0><<<NQ / 8, 256, SMEM_TOTAL>>>(pts, w1a, g1a, bb1a, w1b, g1b, bb1b,
                                                     w1c, g1c, bb1c, 0.1f);
    scale_kernel<64, 1><<<NQ / 8, 256, SMEM_TOTAL>>>(pts, w2a, g2a, bb2a, w2b, g2b, bb2b,
                                                     w2c, g2c, bb2c, 0.2f);
    final_kernel<<<NQ / 32, 256, FINAL_SMEM>>>(b3, (float*)d_out);
}

// round 5
// speedup vs baseline: 1.5436x; 1.1527x over previous
#include <cuda_runtime.h>
#include <math.h>

#define BATCH 2
#define NPTS  4096
#define MQ    4096
#define NQ    (BATCH * MQ)

// scratch
__device__ float g_f1[NQ * 128];
__device__ float g_f2[NQ * 128];
__device__ float g_sx[BATCH * NPTS], g_sy[BATCH * NPTS], g_sz[BATCH * NPTS];
__device__ float g_W3t[256 * 128];   // transposed final weights [c][o]

// ---------------- f32x2 helpers ----------------
typedef unsigned long long u64;
__device__ __forceinline__ u64 pack2(float x) {
    u64 r; asm("mov.b64 %0, {%1,%1};" : "=l"(r) : "f"(x)); return r;
}
__device__ __forceinline__ u64 pack2(float x, float y) {
    u64 r; asm("mov.b64 %0, {%1,%2};" : "=l"(r) : "f"(x), "f"(y)); return r;
}
__device__ __forceinline__ void unpack2(u64 v, float& x, float& y) {
    asm("mov.b64 {%0,%1}, %2;" : "=f"(x), "=f"(y) : "l"(v));
}
__device__ __forceinline__ void ffma2(u64& d, u64 a, u64 b) {
    asm("fma.rn.f32x2 %0, %1, %2, %0;" : "+l"(d) : "l"(a), "l"(b));
}
__device__ __forceinline__ u64 ffma2c(u64 a, u64 b, u64 c) {
    u64 d; asm("fma.rn.f32x2 %0, %1, %2, %3;" : "=l"(d) : "l"(a), "l"(b), "l"(c)); return d;
}

// ---------------- shared memory layout (dynamic, scale kernels) ----------------
// W3q  : float4 [64][32]  (k-major, per-lane float4 of 4 out-groups)  32768 B @ 0
// W2q  : float2 [32][32]  (k-major, per-lane float2 of 2 out-groups)   8192 B @ 32768
// h1p  : u64 [8 warps][32*6]   12288 B @ 40960
// h2p  : u64 [8 warps][64*6]   24576 B @ 53248
// warp scratch: 8 warps * 464 floats  14848 B @ 77824
#define SMEM_TOTAL 92672
#define FINAL_SMEM (32 * 256 * 4 + 64 * 128 * 4)   // 65536

template <int NS, int SCALE>
__global__ void __launch_bounds__(256, 2)
scale_kernel(const float* __restrict__ pts,
             const float* __restrict__ W1, const float* __restrict__ G1, const float* __restrict__ B1,
             const float* __restrict__ W2, const float* __restrict__ G2, const float* __restrict__ B2,
             const float* __restrict__ W3L, const float* __restrict__ G3, const float* __restrict__ B3,
             float radius)
{
    extern __shared__ unsigned char smraw[];
    float4* W3q = (float4*)smraw;
    float2* W2q = (float2*)(smraw + 32768);
    const int tid  = threadIdx.x;
    const int lane = tid & 31;
    const int wid  = tid >> 5;
    u64*   h1p  = (u64*)(smraw + 40960) + wid * 192;
    u64*   h2p  = (u64*)(smraw + 53248) + wid * 384;
    float* wr   = (float*)(smraw + 77824) + wid * 464;
    float* relx = wr;        float* rely = wr + 64;  float* relz = wr + 128;
    float* wgt  = wr + 192;  float* pzv  = wr + 256; float* la   = wr + 320;
    float* lb   = wr + 384;  float* msc  = wr + 448;

    // ---- stage weights (sync happens before MLP) ----
    // W3q[k*32 + l] = { W3L[l*64+k], W3L[(l+32)*64+k], W3L[(l+64)*64+k], W3L[(l+96)*64+k] }
    for (int i = tid; i < 64 * 32; i += 256) {
        int k = i >> 5, l = i & 31;
        W3q[k * 32 + l] = make_float4(W3L[l * 64 + k], W3L[(l + 32) * 64 + k],
                                      W3L[(l + 64) * 64 + k], W3L[(l + 96) * 64 + k]);
    }
    // W2q[k*32 + l] = { W2[l*32+k], W2[(l+32)*32+k] }
    for (int i = tid; i < 32 * 32; i += 256) {
        int k = i >> 5, l = i & 31;
        W2q[k * 32 + l] = make_float2(W2[l * 32 + k], W2[(l + 32) * 32 + k]);
    }

    const int qi = blockIdx.x * 8 + wid;       // query index 0..8191
    const int b  = qi >> 12;
    const int m  = qi & (MQ - 1);
    const float* px = g_sx + b * NPTS;
    const float* py = g_sy + b * NPTS;
    const float* pz = g_sz + b * NPTS;
    const float qx = px[m], qy = py[m], qz = pz[m];
    const float r2 = radius * radius;
    const unsigned lmask = (1u << lane) - 1u;

    // ---------------- warp-synchronous ball query ----------------
    int cnt = 0;
    for (int c = 0; c < NPTS && cnt < NS; c += 32) {
        int p = c + lane;
        float dx = px[p] - qx, dy = py[p] - qy, dz = pz[p] - qz;
        float d2 = dx * dx + dy * dy + dz * dz;
        bool pred = d2 < r2;
        unsigned bal = __ballot_sync(0xffffffffu, pred);
        int pos = cnt + __popc(bal & lmask);
        if (pred && pos < NS) {
            relx[pos] = dx; rely[pos] = dy; relz[pos] = dz;
            wgt[pos]  = fmaxf(radius - sqrtf(d2), 0.0f);
        }
        cnt += __popc(bal);
    }
    cnt = min(cnt, NS);
    __syncwarp();
    // neighbors processed by the MLP: round cnt up to 8 (duplicates beyond that
    // cannot change the max-pool); pad that region with neighbor 0
    const int send = min(NS, (cnt + 7) & ~7);
    {
        float r0x = relx[0], r0y = rely[0], r0z = relz[0], w0 = wgt[0];
        for (int i = cnt + lane; i < send; i += 32) {
            relx[i] = r0x; rely[i] = r0y; relz[i] = r0z; wgt[i] = w0;
        }
    }
    __syncwarp();

    // ---------------- weighted covariance + Σrel (fp64 warp reduce) ----------------
    {
        double acc[10];
        #pragma unroll
        for (int i = 0; i < 10; i++) acc[i] = 0.0;
        #pragma unroll
        for (int si = lane; si < NS; si += 32) {
            // duplicates beyond cnt are exact copies of neighbor 0, matching the
            // reference's replicate-first semantics; use only real + replicated set
            double rx, ry, rz, w;
            if (si < cnt) { rx = relx[si]; ry = rely[si]; rz = relz[si]; w = wgt[si]; }
            else          { rx = relx[0];  ry = rely[0];  rz = relz[0];  w = wgt[0];  }
            acc[0] += w * rx * rx; acc[1] += w * rx * ry; acc[2] += w * rx * rz;
            acc[3] += w * ry * ry; acc[4] += w * ry * rz; acc[5] += w * rz * rz;
            acc[6] += w; acc[7] += rx; acc[8] += ry; acc[9] += rz;
        }
        #pragma unroll
        for (int off = 16; off; off >>= 1) {
            #pragma unroll
            for (int i = 0; i < 10; i++) acc[i] += __shfl_down_sync(0xffffffffu, acc[i], off);
        }
        if (lane == 0) {
            double inv = 1.0 / (acc[6] + 1e-8);
            double a00 = acc[0] * inv, a01 = acc[1] * inv, a02 = acc[2] * inv;
            double a11 = acc[3] * inv, a12 = acc[4] * inv, a22 = acc[5] * inv;
            double zx, zy, zz;
            double p1 = a01 * a01 + a02 * a02 + a12 * a12;
            if (p1 < 1e-30) {
                if (a00 <= a11 && a00 <= a22)      { zx = 1; zy = 0; zz = 0; }
                else if (a11 <= a22)               { zx = 0; zy = 1; zz = 0; }
                else                               { zx = 0; zy = 0; zz = 1; }
            } else {
                double q  = (a00 + a11 + a22) / 3.0;
                double b00 = a00 - q, b11 = a11 - q, b22 = a22 - q;
                double p2 = b00 * b00 + b11 * b11 + b22 * b22 + 2.0 * p1;
                double p  = sqrt(p2 / 6.0);
                double ip = 1.0 / p;
                double c00 = b00 * ip, c01 = a01 * ip, c02 = a02 * ip;
                double c11 = b11 * ip, c12 = a12 * ip, c22 = b22 * ip;
                double detB = c00 * (c11 * c22 - c12 * c12)
                            - c01 * (c01 * c22 - c12 * c02)
                            + c02 * (c01 * c12 - c11 * c02);
                double r = fmin(1.0, fmax(-1.0, 0.5 * detB));
                double phi = acos(r) / 3.0;
                double lmin = q + 2.0 * p * cos(phi + 2.0943951023931953);
                double r0x = a00 - lmin, r0y = a01,        r0z = a02;
                double r1x = a01,        r1y = a11 - lmin, r1z = a12;
                double r2x = a02,        r2y = a12,        r2z = a22 - lmin;
                double v0x = r0y * r1z - r0z * r1y, v0y = r0z * r1x - r0x * r1z, v0z = r0x * r1y - r0y * r1x;
                double v1x = r0y * r2z - r0z * r2y, v1y = r0z * r2x - r0x * r2z, v1z = r0x * r2y - r0y * r2x;
                double v2x = r1y * r2z - r1z * r2y, v2y = r1z * r2x - r1x * r2z, v2z = r1x * r2y - r1y * r2x;
                double n0 = v0x * v0x + v0y * v0y + v0z * v0z;
                double n1 = v1x * v1x + v1y * v1y + v1z * v1z;
                double n2 = v2x * v2x + v2y * v2y + v2z * v2z;
                double vx, vy, vz, nn;
                if (n0 >= n1 && n0 >= n2)      { vx = v0x; vy = v0y; vz = v0z; nn = n0; }
                else if (n1 >= n2)             { vx = v1x; vy = v1y; vz = v1z; nn = n1; }
                else                           { vx = v2x; vy = v2y; vz = v2z; nn = n2; }
                double inr = (nn > 0.0) ? (1.0 / sqrt(nn)) : 0.0;
                zx = vx * inr; zy = vy * inr; zz = vz * inr;
            }
            double dotz = acc[7] * zx + acc[8] * zy + acc[9] * zz;
            if (dotz > 0.0) { zx = -zx; zy = -zy; zz = -zz; }
            msc[0] = (float)zx; msc[1] = (float)zy; msc[2] = (float)zz;
        }
    }
    __syncwarp();

    {   // pz per neighbor
        float zx = msc[0], zy = msc[1], zz = msc[2];
        for (int i = lane; i < send; i += 32)
            pzv[i] = relx[i] * zx + rely[i] * zy + relz[i] * zz;
    }
    __syncwarp();

    {   // xv accumulation (fp64 warp reduce) — duplicates replicate neighbor 0
        double zx = msc[0], zy = msc[1], zz = msc[2];
        double sx = 0, sy = 0, sz = 0;
        #pragma unroll
        for (int si = lane; si < NS; si += 32) {
            int j = (si < cnt) ? si : 0;
            double pzd = pzv[j], w = wgt[j];
            double t = (w * w) * (pzd * pzd);
            sx += t * (relx[j] - pzd * zx);
            sy += t * (rely[j] - pzd * zy);
            sz += t * (relz[j] - pzd * zz);
        }
        #pragma unroll
        for (int off = 16; off; off >>= 1) {
            sx += __shfl_down_sync(0xffffffffu, sx, off);
            sy += __shfl_down_sync(0xffffffffu, sy, off);
            sz += __shfl_down_sync(0xffffffffu, sz, off);
        }
        if (lane == 0) {
            double nrm = sqrt(sx * sx + sy * sy + sz * sz);
            double inr = 1.0 / (nrm + 1e-8);
            float xx = (float)(sx * inr), xy = (float)(sy * inr), xz = (float)(sz * inr);
            msc[3] = xx; msc[4] = xy; msc[5] = xz;
            float zx2 = msc[0], zy2 = msc[1], zz2 = msc[2];
            msc[6] = zy2 * xz - zz2 * xy;
            msc[7] = zz2 * xx - zx2 * xz;
            msc[8] = zx2 * xy - zy2 * xx;
        }
    }
    __syncwarp();

    {   // LRF in-plane coordinates
        float xx = msc[3], xy = msc[4], xz = msc[5];
        float yx = msc[6], yy = msc[7], yz = msc[8];
        for (int i = lane; i < send; i += 32) {
            float rx = relx[i], ry = rely[i], rz = relz[i];
            la[i] = rx * xx + ry * xy + rz * xz;
            lb[i] = rx * yx + ry * yy + rz * yz;
        }
    }

    __syncthreads();   // weights staged + all warps' LRF data in place

    // ---------------- packed MLP 3->32->64->128 + max over neighbors ----------------
    const float bns = 0.99999500003749968752f;  // 1/sqrt(1+1e-5)
    const float wa0 = W1[lane * 3 + 0], wa1 = W1[lane * 3 + 1], wa2 = W1[lane * 3 + 2];
    const float s1  = G1[lane] * bns,  b1v = B1[lane];
    const u64 s2pA = pack2(G2[lane] * bns),        b2pA = pack2(B2[lane]);
    const u64 s2pB = pack2(G2[lane + 32] * bns),   b2pB = pack2(B2[lane + 32]);
    u64 s3p[4], b3p[4];
    #pragma unroll
    for (int j = 0; j < 4; j++) { s3p[j] = pack2(G3[lane + 32 * j] * bns); b3p[j] = pack2(B3[lane + 32 * j]); }

    float fm[4] = {0.f, 0.f, 0.f, 0.f};

    for (int s0 = 0; s0 < send; s0 += 8) {
        // layer 1: channel = lane, 8 neighbors -> 4 pairs (u64 stride 6 per channel)
        #pragma unroll
        for (int p = 0; p < 4; p++) {
            int n0 = s0 + 2 * p;
            float v0 = fmaf(wa0, la[n0],     fmaf(wa1, lb[n0],     wa2 * pzv[n0]));
            float v1 = fmaf(wa0, la[n0 + 1], fmaf(wa1, lb[n0 + 1], wa2 * pzv[n0 + 1]));
            v0 = fmaxf(fmaf(v0, s1, b1v), 0.f);
            v1 = fmaxf(fmaf(v1, s1, b1v), 0.f);
            h1p[lane * 6 + p] = pack2(v0, v1);
        }
        __syncwarp();

        // layer 2: out channels (lane, lane+32); weights via float2 + reg-dup
        u64 accA[4] = {0, 0, 0, 0}, accB[4] = {0, 0, 0, 0};
        #pragma unroll
        for (int k = 0; k < 32; k++) {
            float2 w = W2q[k * 32 + lane];
            u64 wA = pack2(w.x), wB = pack2(w.y);
            ulonglong2 h01 = *(const ulonglong2*)&h1p[k * 6];
            ulonglong2 h23 = *(const ulonglong2*)&h1p[k * 6 + 2];
            ffma2(accA[0], wA, h01.x); ffma2(accB[0], wB, h01.x);
            ffma2(accA[1], wA, h01.y); ffma2(accB[1], wB, h01.y);
            ffma2(accA[2], wA, h23.x); ffma2(accB[2], wB, h23.x);
            ffma2(accA[3], wA, h23.y); ffma2(accB[3], wB, h23.y);
        }
        #pragma unroll
        for (int p = 0; p < 4; p++) {
            u64 t = ffma2c(accA[p], s2pA, b2pA);
            float x, y; unpack2(t, x, y);
            h2p[lane * 6 + p] = pack2(fmaxf(x, 0.f), fmaxf(y, 0.f));
            t = ffma2c(accB[p], s2pB, b2pB);
            unpack2(t, x, y);
            h2p[(lane + 32) * 6 + p] = pack2(fmaxf(x, 0.f), fmaxf(y, 0.f));
        }
        __syncwarp();

        // layer 3: 4 output groups x 4 neighbor pairs; weights via float4 + reg-dup
        u64 acc3[16];
        #pragma unroll
        for (int i = 0; i < 16; i++) acc3[i] = 0;
        #pragma unroll 8
        for (int k = 0; k < 64; k++) {
            float4 w4 = W3q[k * 32 + lane];
            u64 wp0 = pack2(w4.x), wp1 = pack2(w4.y), wp2 = pack2(w4.z), wp3 = pack2(w4.w);
            ulonglong2 h01 = *(const ulonglong2*)&h2p[k * 6];
            ulonglong2 h23 = *(const ulonglong2*)&h2p[k * 6 + 2];
            ffma2(acc3[0],  wp0, h01.x); ffma2(acc3[1],  wp0, h01.y);
            ffma2(acc3[2],  wp0, h23.x); ffma2(acc3[3],  wp0, h23.y);
            ffma2(acc3[4],  wp1, h01.x); ffma2(acc3[5],  wp1, h01.y);
            ffma2(acc3[6],  wp1, h23.x); ffma2(acc3[7],  wp1, h23.y);
            ffma2(acc3[8],  wp2, h01.x); ffma2(acc3[9],  wp2, h01.y);
            ffma2(acc3[10], wp2, h23.x); ffma2(acc3[11], wp2, h23.y);
            ffma2(acc3[12], wp3, h01.x); ffma2(acc3[13], wp3, h01.y);
            ffma2(acc3[14], wp3, h23.x); ffma2(acc3[15], wp3, h23.y);
        }
        #pragma unroll
        for (int j = 0; j < 4; j++) {
            #pragma unroll
            for (int p = 0; p < 4; p++) {
                u64 t = ffma2c(acc3[j * 4 + p], s3p[j], b3p[j]);
                float x, y; unpack2(t, x, y);
                fm[j] = fmaxf(fm[j], fmaxf(x, y));   // fm>=0 handles the ReLU clamp
            }
        }
        __syncwarp();
    }

    float* fout = (SCALE == 0) ? g_f1 : g_f2;
    #pragma unroll
    for (int j = 0; j < 4; j++)
        fout[(size_t)qi * 128 + lane + 32 * j] = fm[j];
}

// ---------------- SoA transpose of the point cloud ----------------
__global__ void soa_kernel(const float* __restrict__ pts)
{
    int i = blockIdx.x * blockDim.x + threadIdx.x;
    if (i < BATCH * NPTS) {
        g_sx[i] = pts[i * 3 + 0];
        g_sy[i] = pts[i * 3 + 1];
        g_sz[i] = pts[i * 3 + 2];
    }
}

// ---------------- transpose final weights [o][c] -> [c][o] ----------------
__global__ void w3t_kernel(const float* __restrict__ w3)
{
    int i = blockIdx.x * blockDim.x + threadIdx.x;   // 128*256
    if (i < 128 * 256) {
        int o = i >> 8, c = i & 255;
        g_W3t[c * 128 + o] = w3[i];
    }
}

// ---------------- final linear: tiled, 32 queries/block (dynamic smem) ----------------
__global__ void __launch_bounds__(256)
final_kernel(const float* __restrict__ B3f, float* __restrict__ out)
{
    extern __shared__ float fsm[];
    float* feats = fsm;            // 32 * 256
    float* wt    = fsm + 32 * 256; // 64 * 128
    const int tid = threadIdx.x, lane = tid & 31, wid = tid >> 5;
    const int q0 = blockIdx.x * 32;

    for (int i = tid; i < 32 * 128; i += 256) {
        int q = i >> 7, c = i & 127;
        feats[q * 256 + c]       = g_f1[(size_t)(q0 + q) * 128 + c];
        feats[q * 256 + 128 + c] = g_f2[(size_t)(q0 + q) * 128 + c];
    }

    float acc[4][4];   // [local query][output group]
    #pragma unroll
    for (int ql = 0; ql < 4; ql++)
        #pragma unroll
        for (int j = 0; j < 4; j++) acc[ql][j] = 0.f;

    const int qbase = wid * 4;
    for (int ct = 0; ct < 4; ct++) {
        __syncthreads();
        for (int i = tid; i < 64 * 128; i += 256)
            wt[i] = g_W3t[ct * 64 * 128 + i];
        __syncthreads();
        #pragma unroll 8
        for (int c = 0; c < 64; c++) {
            float w0 = wt[c * 128 + lane];
            float w1 = wt[c * 128 + lane + 32];
            float w2 = wt[c * 128 + lane + 64];
            float w3v = wt[c * 128 + lane + 96];
            #pragma unroll
            for (int ql = 0; ql < 4; ql++) {
                float f = feats[(qbase + ql) * 256 + ct * 64 + c];
                acc[ql][0] = fmaf(w0, f, acc[ql][0]);
                acc[ql][1] = fmaf(w1, f, acc[ql][1]);
                acc[ql][2] = fmaf(w2, f, acc[ql][2]);
                acc[ql][3] = fmaf(w3v, f, acc[ql][3]);
            }
        }
    }
    #pragma unroll
    for (int ql = 0; ql < 4; ql++)
        #pragma unroll
        for (int j = 0; j < 4; j++)
            out[(size_t)(q0 + qbase + ql) * 128 + lane + 32 * j] = acc[ql][j] + B3f[lane + 32 * j];
}

extern "C" void kernel_launch(void* const* d_in, const int* in_sizes, int n_in,
                              void* d_out, int out_size)
{
    const float* pts  = (const float*)d_in[0];
    const float* w1a  = (const float*)d_in[1];
    const float* g1a  = (const float*)d_in[2];
    const float* bb1a = (const float*)d_in[3];
    const float* w1b  = (const float*)d_in[4];
    const float* g1b  = (const float*)d_in[5];
    const float* bb1b = (const float*)d_in[6];
    const float* w1c  = (const float*)d_in[7];
    const float* g1c  = (const float*)d_in[8];
    const float* bb1c = (const float*)d_in[9];
    const float* w2a  = (const float*)d_in[10];
    const float* g2a  = (const float*)d_in[11];
    const float* bb2a = (const float*)d_in[12];
    const float* w2b  = (const float*)d_in[13];
    const float* g2b  = (const float*)d_in[14];
    const float* bb2b = (const float*)d_in[15];
    const float* w2c  = (const float*)d_in[16];
    const float* g2c  = (const float*)d_in[17];
    const float* bb2c = (const float*)d_in[18];
    const float* w3   = (const float*)d_in[19];
    const float* b3   = (const float*)d_in[20];

    cudaFuncSetAttribute(scale_kernel<32, 0>, cudaFuncAttributeMaxDynamicSharedMemorySize, SMEM_TOTAL);
    cudaFuncSetAttribute(scale_kernel<64, 1>, cudaFuncAttributeMaxDynamicSharedMemorySize, SMEM_TOTAL);
    cudaFuncSetAttribute(final_kernel, cudaFuncAttributeMaxDynamicSharedMemorySize, FINAL_SMEM);

    soa_kernel<<<(BATCH * NPTS + 255) / 256, 256>>>(pts);
    w3t_kernel<<<(128 * 256 + 255) / 256, 256>>>(w3);
    scale_kernel<32, 0><<<NQ / 8, 256, SMEM_TOTAL>>>(pts, w1a, g1a, bb1a, w1b, g1b, bb1b,
                                                     w1c, g1c, bb1c, 0.1f);
    scale_kernel<64, 1><<<NQ / 8, 256, SMEM_TOTAL>>>(pts, w2a, g2a, bb2a, w2b, g2b, bb2b,
                                                     w2c, g2c, bb2c, 0.2f);
    final_kernel<<<NQ / 32, 256, FINAL_SMEM>>>(b3, (float*)d_out);
}

// round 6
// speedup vs baseline: 1.5974x; 1.0349x over previous
#include <cuda_runtime.h>
#include <math.h>

#define BATCH 2
#define NPTS  4096
#define MQ    4096
#define NQ    (BATCH * MQ)

// scratch
__device__ float g_f1[NQ * 128];
__device__ float g_f2[NQ * 128];
__device__ float g_sx[BATCH * NPTS], g_sy[BATCH * NPTS], g_sz[BATCH * NPTS];
__device__ float g_W3t[256 * 128];   // transposed final weights [c][o]

// ---------------- f32x2 helpers ----------------
typedef unsigned long long u64;
__device__ __forceinline__ u64 pack2(float x) {
    u64 r; asm("mov.b64 %0, {%1,%1};" : "=l"(r) : "f"(x)); return r;
}
__device__ __forceinline__ u64 pack2(float x, float y) {
    u64 r; asm("mov.b64 %0, {%1,%2};" : "=l"(r) : "f"(x), "f"(y)); return r;
}
__device__ __forceinline__ void unpack2(u64 v, float& x, float& y) {
    asm("mov.b64 {%0,%1}, %2;" : "=f"(x), "=f"(y) : "l"(v));
}
__device__ __forceinline__ void ffma2(u64& d, u64 a, u64 b) {
    asm("fma.rn.f32x2 %0, %1, %2, %0;" : "+l"(d) : "l"(a), "l"(b));
}
__device__ __forceinline__ u64 ffma2c(u64 a, u64 b, u64 c) {
    u64 d; asm("fma.rn.f32x2 %0, %1, %2, %3;" : "=l"(d) : "l"(a), "l"(b), "l"(c)); return d;
}

// ---------------- shared memory layout (dynamic) ----------------
// W3q  : float4 [64][32]                 32768 B @ 0
// W2q  : float2 [32][32]                  8192 B @ 32768
// h1   : u64 [8 warps][32 k][10]  (8 pairs + 2 pad)  20480 B @ 40960
// h2   : u64 [8 warps][64 k][10]                     40960 B @ 61440
// scratch: 8 warps * 336 floats                      10752 B @ 102400
#define SMEM_TOTAL 113152
#define FINAL_SMEM (32 * 256 * 4 + 64 * 128 * 4)   // 65536

__global__ void __launch_bounds__(256, 2)
scale_kernel(const float* __restrict__ w1a, const float* __restrict__ g1a, const float* __restrict__ b1a,
             const float* __restrict__ w1b, const float* __restrict__ g1b, const float* __restrict__ b1b,
             const float* __restrict__ w1c, const float* __restrict__ g1c, const float* __restrict__ b1c,
             const float* __restrict__ w2a, const float* __restrict__ g2a, const float* __restrict__ b2a,
             const float* __restrict__ w2b, const float* __restrict__ g2b, const float* __restrict__ b2b,
             const float* __restrict__ w2c, const float* __restrict__ g2c, const float* __restrict__ b2c)
{
    extern __shared__ unsigned char smraw[];
    float4* W3q = (float4*)smraw;
    float2* W2q = (float2*)(smraw + 32768);
    const int tid  = threadIdx.x;
    const int lane = tid & 31;
    const int wid  = tid >> 5;
    u64*   h1w = (u64*)(smraw + 40960 + wid * 2560);
    u64*   h2w = (u64*)(smraw + 61440 + wid * 5120);
    float* wr  = (float*)(smraw + 102400) + wid * 336;
    float* relx = wr;        float* rely = wr + 64;  float* relz = wr + 128;
    float* wgt  = wr + 192;  float* pzv  = wr + 256; float* msc  = wr + 320;
    float* la = relx;  float* lb = rely;   // aliases, valid after LRF phase

    // scale-2 blocks first (longer work -> better tail packing)
    const bool sc2 = blockIdx.x < 1024;
    const float* W1  = sc2 ? w2a : w1a;  const float* G1 = sc2 ? g2a : g1a;  const float* B1 = sc2 ? b2a : b1a;
    const float* W2  = sc2 ? w2b : w1b;  const float* G2 = sc2 ? g2b : g1b;  const float* B2 = sc2 ? b2b : b1b;
    const float* W3L = sc2 ? w2c : w1c;  const float* G3 = sc2 ? g2c : g1c;  const float* B3 = sc2 ? b2c : b1c;
    const float radius = sc2 ? 0.2f : 0.1f;
    const int   NS     = sc2 ? 64 : 32;
    float*      fout   = sc2 ? g_f2 : g_f1;

    // ---- stage weights (sync happens before MLP) ----
    for (int i = tid; i < 64 * 32; i += 256) {
        int k = i >> 5, l = i & 31;
        W3q[k * 32 + l] = make_float4(W3L[l * 64 + k], W3L[(l + 32) * 64 + k],
                                      W3L[(l + 64) * 64 + k], W3L[(l + 96) * 64 + k]);
    }
    for (int i = tid; i < 32 * 32; i += 256) {
        int k = i >> 5, l = i & 31;
        W2q[k * 32 + l] = make_float2(W2[l * 32 + k], W2[(l + 32) * 32 + k]);
    }

    const int qi = (blockIdx.x & 1023) * 8 + wid;   // query index 0..8191
    const int b  = qi >> 12;
    const int m  = qi & (MQ - 1);
    const float* px = g_sx + b * NPTS;
    const float* py = g_sy + b * NPTS;
    const float* pz = g_sz + b * NPTS;
    const float qx = px[m], qy = py[m], qz = pz[m];
    const float r2 = radius * radius;
    const unsigned lmask = (1u << lane) - 1u;

    // ---------------- warp-synchronous ball query ----------------
    int cnt = 0;
    for (int c = 0; c < NPTS && cnt < NS; c += 32) {
        int p = c + lane;
        float dx = px[p] - qx, dy = py[p] - qy, dz = pz[p] - qz;
        float d2 = dx * dx + dy * dy + dz * dz;
        bool pred = d2 < r2;
        unsigned bal = __ballot_sync(0xffffffffu, pred);
        int pos = cnt + __popc(bal & lmask);
        if (pred && pos < NS) {
            relx[pos] = dx; rely[pos] = dy; relz[pos] = dz;
            wgt[pos]  = fmaxf(radius - sqrtf(d2), 0.0f);
        }
        cnt += __popc(bal);
    }
    cnt = min(cnt, NS);
    __syncwarp();
    const int send = min(NS, (cnt + 7) & ~7);
    {
        float r0x = relx[0], r0y = rely[0], r0z = relz[0], w0 = wgt[0];
        for (int i = cnt + lane; i < send; i += 32) {
            relx[i] = r0x; rely[i] = r0y; relz[i] = r0z; wgt[i] = w0;
        }
    }
    __syncwarp();

    // ---------------- weighted covariance + Σrel (fp64 warp reduce) ----------------
    {
        double acc[10];
        #pragma unroll
        for (int i = 0; i < 10; i++) acc[i] = 0.0;
        for (int si = lane; si < NS; si += 32) {
            int j = (si < cnt) ? si : 0;    // replicate-first semantics
            double rx = relx[j], ry = rely[j], rz = relz[j], w = wgt[j];
            acc[0] += w * rx * rx; acc[1] += w * rx * ry; acc[2] += w * rx * rz;
            acc[3] += w * ry * ry; acc[4] += w * ry * rz; acc[5] += w * rz * rz;
            acc[6] += w; acc[7] += rx; acc[8] += ry; acc[9] += rz;
        }
        #pragma unroll
        for (int off = 16; off; off >>= 1) {
            #pragma unroll
            for (int i = 0; i < 10; i++) acc[i] += __shfl_down_sync(0xffffffffu, acc[i], off);
        }
        if (lane == 0) {
            double inv = 1.0 / (acc[6] + 1e-8);
            double a00 = acc[0] * inv, a01 = acc[1] * inv, a02 = acc[2] * inv;
            double a11 = acc[3] * inv, a12 = acc[4] * inv, a22 = acc[5] * inv;
            double zx, zy, zz;
            double p1 = a01 * a01 + a02 * a02 + a12 * a12;
            if (p1 < 1e-30) {
                if (a00 <= a11 && a00 <= a22)      { zx = 1; zy = 0; zz = 0; }
                else if (a11 <= a22)               { zx = 0; zy = 1; zz = 0; }
                else                               { zx = 0; zy = 0; zz = 1; }
            } else {
                double q  = (a00 + a11 + a22) / 3.0;
                double b00 = a00 - q, b11 = a11 - q, b22 = a22 - q;
                double p2 = b00 * b00 + b11 * b11 + b22 * b22 + 2.0 * p1;
                double p  = sqrt(p2 / 6.0);
                double ip = 1.0 / p;
                double c00 = b00 * ip, c01 = a01 * ip, c02 = a02 * ip;
                double c11 = b11 * ip, c12 = a12 * ip, c22 = b22 * ip;
                double detB = c00 * (c11 * c22 - c12 * c12)
                            - c01 * (c01 * c22 - c12 * c02)
                            + c02 * (c01 * c12 - c11 * c02);
                double r = fmin(1.0, fmax(-1.0, 0.5 * detB));
                double phi = acos(r) / 3.0;
                double lmin = q + 2.0 * p * cos(phi + 2.0943951023931953);
                double r0x = a00 - lmin, r0y = a01,        r0z = a02;
                double r1x = a01,        r1y = a11 - lmin, r1z = a12;
                double r2x = a02,        r2y = a12,        r2z = a22 - lmin;
                double v0x = r0y * r1z - r0z * r1y, v0y = r0z * r1x - r0x * r1z, v0z = r0x * r1y - r0y * r1x;
                double v1x = r0y * r2z - r0z * r2y, v1y = r0z * r2x - r0x * r2z, v1z = r0x * r2y - r0y * r2x;
                double v2x = r1y * r2z - r1z * r2y, v2y = r1z * r2x - r1x * r2z, v2z = r1x * r2y - r1y * r2x;
                double n0 = v0x * v0x + v0y * v0y + v0z * v0z;
                double n1 = v1x * v1x + v1y * v1y + v1z * v1z;
                double n2 = v2x * v2x + v2y * v2y + v2z * v2z;
                double vx, vy, vz, nn;
                if (n0 >= n1 && n0 >= n2)      { vx = v0x; vy = v0y; vz = v0z; nn = n0; }
                else if (n1 >= n2)             { vx = v1x; vy = v1y; vz = v1z; nn = n1; }
                else                           { vx = v2x; vy = v2y; vz = v2z; nn = n2; }
                double inr = (nn > 0.0) ? (1.0 / sqrt(nn)) : 0.0;
                zx = vx * inr; zy = vy * inr; zz = vz * inr;
            }
            double dotz = acc[7] * zx + acc[8] * zy + acc[9] * zz;
            if (dotz > 0.0) { zx = -zx; zy = -zy; zz = -zz; }
            msc[0] = (float)zx; msc[1] = (float)zy; msc[2] = (float)zz;
        }
    }
    __syncwarp();

    {   // pz per neighbor
        float zx = msc[0], zy = msc[1], zz = msc[2];
        for (int i = lane; i < send; i += 32)
            pzv[i] = relx[i] * zx + rely[i] * zy + relz[i] * zz;
    }
    __syncwarp();

    {   // xv accumulation (fp64 warp reduce)
        double zx = msc[0], zy = msc[1], zz = msc[2];
        double sx = 0, sy = 0, sz = 0;
        for (int si = lane; si < NS; si += 32) {
            int j = (si < cnt) ? si : 0;
            double pzd = pzv[j], w = wgt[j];
            double t = (w * w) * (pzd * pzd);
            sx += t * (relx[j] - pzd * zx);
            sy += t * (rely[j] - pzd * zy);
            sz += t * (relz[j] - pzd * zz);
        }
        #pragma unroll
        for (int off = 16; off; off >>= 1) {
            sx += __shfl_down_sync(0xffffffffu, sx, off);
            sy += __shfl_down_sync(0xffffffffu, sy, off);
            sz += __shfl_down_sync(0xffffffffu, sz, off);
        }
        if (lane == 0) {
            double nrm = sqrt(sx * sx + sy * sy + sz * sz);
            double inr = 1.0 / (nrm + 1e-8);
            float xx = (float)(sx * inr), xy = (float)(sy * inr), xz = (float)(sz * inr);
            msc[3] = xx; msc[4] = xy; msc[5] = xz;
            float zx2 = msc[0], zy2 = msc[1], zz2 = msc[2];
            msc[6] = zy2 * xz - zz2 * xy;
            msc[7] = zz2 * xx - zx2 * xz;
            msc[8] = zx2 * xy - zy2 * xx;
        }
    }
    __syncwarp();

    {   // LRF in-plane coords; overwrite relx->la, rely->lb (relz/wgt now dead)
        float xx = msc[3], xy = msc[4], xz = msc[5];
        float yx = msc[6], yy = msc[7], yz = msc[8];
        for (int i = lane; i < send; i += 32) {
            float rx = relx[i], ry = rely[i], rz = relz[i];
            float va = rx * xx + ry * xy + rz * xz;
            float vb = rx * yx + ry * yy + rz * yz;
            relx[i] = va; rely[i] = vb;
        }
    }

    __syncthreads();   // weights staged + all warps' LRF data in place

    // ---------------- packed MLP 3->32->64->128 + max over neighbors ----------------
    const float bns = 0.99999500003749968752f;  // 1/sqrt(1+1e-5)
    const float wa0 = W1[lane * 3 + 0], wa1 = W1[lane * 3 + 1], wa2 = W1[lane * 3 + 2];
    const float s1  = G1[lane] * bns,  b1v = B1[lane];

    float fm[4] = {0.f, 0.f, 0.f, 0.f};
    int s0 = 0;

    // ======== 16-neighbor macro-chunks ========
    for (; s0 + 16 <= send; s0 += 16) {
        // layer 1: 16 neighbors -> 8 pairs (h1 row stride 10 u64)
        #pragma unroll
        for (int p = 0; p < 8; p++) {
            int n0 = s0 + 2 * p;
            float v0 = fmaf(wa0, la[n0],     fmaf(wa1, lb[n0],     wa2 * pzv[n0]));
            float v1 = fmaf(wa0, la[n0 + 1], fmaf(wa1, lb[n0 + 1], wa2 * pzv[n0 + 1]));
            v0 = fmaxf(fmaf(v0, s1, b1v), 0.f);
            v1 = fmaxf(fmaf(v1, s1, b1v), 0.f);
            h1w[lane * 10 + p] = pack2(v0, v1);
        }
        __syncwarp();

        // layer 2: 32 -> 64, out channels (lane, lane+32)
        u64 acc2[16];
        #pragma unroll
        for (int i = 0; i < 16; i++) acc2[i] = 0;
        #pragma unroll 4
        for (int k = 0; k < 32; k++) {
            float2 w = W2q[k * 32 + lane];
            u64 wA = pack2(w.x), wB = pack2(w.y);
            ulonglong2 t01 = *(const ulonglong2*)&h1w[k * 10];
            ulonglong2 t23 = *(const ulonglong2*)&h1w[k * 10 + 2];
            ulonglong2 t45 = *(const ulonglong2*)&h1w[k * 10 + 4];
            ulonglong2 t67 = *(const ulonglong2*)&h1w[k * 10 + 6];
            u64 hh[8] = {t01.x, t01.y, t23.x, t23.y, t45.x, t45.y, t67.x, t67.y};
            #pragma unroll
            for (int p = 0; p < 8; p++) { ffma2(acc2[p], wA, hh[p]); ffma2(acc2[8 + p], wB, hh[p]); }
        }
        {
            u64 sA = pack2(G2[lane] * bns),      bA = pack2(B2[lane]);
            u64 sB = pack2(G2[lane + 32] * bns), bB = pack2(B2[lane + 32]);
            #pragma unroll
            for (int p = 0; p < 8; p++) {
                u64 t = ffma2c(acc2[p], sA, bA);
                float x, y; unpack2(t, x, y);
                h2w[lane * 10 + p] = pack2(fmaxf(x, 0.f), fmaxf(y, 0.f));
                t = ffma2c(acc2[8 + p], sB, bB);
                unpack2(t, x, y);
                h2w[(lane + 32) * 10 + p] = pack2(fmaxf(x, 0.f), fmaxf(y, 0.f));
            }
        }
        __syncwarp();

        // layer 3: 64 -> 128, 4 out-groups x 8 pairs
        u64 acc3[32];
        #pragma unroll
        for (int i = 0; i < 32; i++) acc3[i] = 0;
        #pragma unroll 4
        for (int k = 0; k < 64; k++) {
            float4 w4 = W3q[k * 32 + lane];
            u64 wp0 = pack2(w4.x), wp1 = pack2(w4.y), wp2 = pack2(w4.z), wp3 = pack2(w4.w);
            ulonglong2 t01 = *(const ulonglong2*)&h2w[k * 10];
            ulonglong2 t23 = *(const ulonglong2*)&h2w[k * 10 + 2];
            ulonglong2 t45 = *(const ulonglong2*)&h2w[k * 10 + 4];
            ulonglong2 t67 = *(const ulonglong2*)&h2w[k * 10 + 6];
            u64 hh[8] = {t01.x, t01.y, t23.x, t23.y, t45.x, t45.y, t67.x, t67.y};
            #pragma unroll
            for (int p = 0; p < 8; p++) {
                ffma2(acc3[p],      wp0, hh[p]);
                ffma2(acc3[8 + p],  wp1, hh[p]);
                ffma2(acc3[16 + p], wp2, hh[p]);
                ffma2(acc3[24 + p], wp3, hh[p]);
            }
        }
        #pragma unroll
        for (int j = 0; j < 4; j++) {
            u64 s3 = pack2(G3[lane + 32 * j] * bns), b3 = pack2(B3[lane + 32 * j]);
            #pragma unroll
            for (int p = 0; p < 8; p++) {
                u64 t = ffma2c(acc3[j * 8 + p], s3, b3);
                float x, y; unpack2(t, x, y);
                fm[j] = fmaxf(fm[j], fmaxf(x, y));
            }
        }
        __syncwarp();
    }

    // ======== 8-neighbor tail chunk ========
    if (s0 < send) {
        #pragma unroll
        for (int p = 0; p < 4; p++) {
            int n0 = s0 + 2 * p;
            float v0 = fmaf(wa0, la[n0],     fmaf(wa1, lb[n0],     wa2 * pzv[n0]));
            float v1 = fmaf(wa0, la[n0 + 1], fmaf(wa1, lb[n0 + 1], wa2 * pzv[n0 + 1]));
            v0 = fmaxf(fmaf(v0, s1, b1v), 0.f);
            v1 = fmaxf(fmaf(v1, s1, b1v), 0.f);
            h1w[lane * 10 + p] = pack2(v0, v1);
        }
        __syncwarp();

        u64 acc2[8];
        #pragma unroll
        for (int i = 0; i < 8; i++) acc2[i] = 0;
        #pragma unroll 4
        for (int k = 0; k < 32; k++) {
            float2 w = W2q[k * 32 + lane];
            u64 wA = pack2(w.x), wB = pack2(w.y);
            ulonglong2 t01 = *(const ulonglong2*)&h1w[k * 10];
            ulonglong2 t23 = *(const ulonglong2*)&h1w[k * 10 + 2];
            u64 hh[4] = {t01.x, t01.y, t23.x, t23.y};
            #pragma unroll
            for (int p = 0; p < 4; p++) { ffma2(acc2[p], wA, hh[p]); ffma2(acc2[4 + p], wB, hh[p]); }
        }
        {
            u64 sA = pack2(G2[lane] * bns),      bA = pack2(B2[lane]);
            u64 sB = pack2(G2[lane + 32] * bns), bB = pack2(B2[lane + 32]);
            #pragma unroll
            for (int p = 0; p < 4; p++) {
                u64 t = ffma2c(acc2[p], sA, bA);
                float x, y; unpack2(t, x, y);
                h2w[lane * 10 + p] = pack2(fmaxf(x, 0.f), fmaxf(y, 0.f));
                t = ffma2c(acc2[4 + p], sB, bB);
                unpack2(t, x, y);
                h2w[(lane + 32) * 10 + p] = pack2(fmaxf(x, 0.f), fmaxf(y, 0.f));
            }
        }
        __syncwarp();

        u64 acc3[16];
        #pragma unroll
        for (int i = 0; i < 16; i++) acc3[i] = 0;
        #pragma unroll 4
        for (int k = 0; k < 64; k++) {
            float4 w4 = W3q[k * 32 + lane];
            u64 wp0 = pack2(w4.x), wp1 = pack2(w4.y), wp2 = pack2(w4.z), wp3 = pack2(w4.w);
            ulonglong2 t01 = *(const ulonglong2*)&h2w[k * 10];
            ulonglong2 t23 = *(const ulonglong2*)&h2w[k * 10 + 2];
            u64 hh[4] = {t01.x, t01.y, t23.x, t23.y};
            #pragma unroll
            for (int p = 0; p < 4; p++) {
                ffma2(acc3[p],      wp0, hh[p]);
                ffma2(acc3[4 + p],  wp1, hh[p]);
                ffma2(acc3[8 + p],  wp2, hh[p]);
                ffma2(acc3[12 + p], wp3, hh[p]);
            }
        }
        #pragma unroll
        for (int j = 0; j < 4; j++) {
            u64 s3 = pack2(G3[lane + 32 * j] * bns), b3 = pack2(B3[lane + 32 * j]);
            #pragma unroll
            for (int p = 0; p < 4; p++) {
                u64 t = ffma2c(acc3[j * 4 + p], s3, b3);
                float x, y; unpack2(t, x, y);
                fm[j] = fmaxf(fm[j], fmaxf(x, y));
            }
        }
    }

    #pragma unroll
    for (int j = 0; j < 4; j++)
        fout[(size_t)qi * 128 + lane + 32 * j] = fm[j];
}

// ---------------- SoA transpose of the point cloud ----------------
__global__ void soa_kernel(const float* __restrict__ pts)
{
    int i = blockIdx.x * blockDim.x + threadIdx.x;
    if (i < BATCH * NPTS) {
        g_sx[i] = pts[i * 3 + 0];
        g_sy[i] = pts[i * 3 + 1];
        g_sz[i] = pts[i * 3 + 2];
    }
}

// ---------------- transpose final weights [o][c] -> [c][o] ----------------
__global__ void w3t_kernel(const float* __restrict__ w3)
{
    int i = blockIdx.x * blockDim.x + threadIdx.x;   // 128*256
    if (i < 128 * 256) {
        int o = i >> 8, c = i & 255;
        g_W3t[c * 128 + o] = w3[i];
    }
}

// ---------------- final linear: tiled, 32 queries/block (dynamic smem) ----------------
__global__ void __launch_bounds__(256)
final_kernel(const float* __restrict__ B3f, float* __restrict__ out)
{
    extern __shared__ float fsm[];
    float* feats = fsm;            // 32 * 256
    float* wt    = fsm + 32 * 256; // 64 * 128
    const int tid = threadIdx.x, lane = tid & 31, wid = tid >> 5;
    const int q0 = blockIdx.x * 32;

    for (int i = tid; i < 32 * 128; i += 256) {
        int q = i >> 7, c = i & 127;
        feats[q * 256 + c]       = g_f1[(size_t)(q0 + q) * 128 + c];
        feats[q * 256 + 128 + c] = g_f2[(size_t)(q0 + q) * 128 + c];
    }

    float acc[4][4];
    #pragma unroll
    for (int ql = 0; ql < 4; ql++)
        #pragma unroll
        for (int j = 0; j < 4; j++) acc[ql][j] = 0.f;

    const int qbase = wid * 4;
    for (int ct = 0; ct < 4; ct++) {
        __syncthreads();
        for (int i = tid; i < 64 * 128; i += 256)
            wt[i] = g_W3t[ct * 64 * 128 + i];
        __syncthreads();
        #pragma unroll 8
        for (int c = 0; c < 64; c++) {
            float w0 = wt[c * 128 + lane];
            float w1 = wt[c * 128 + lane + 32];
            float w2 = wt[c * 128 + lane + 64];
            float w3v = wt[c * 128 + lane + 96];
            #pragma unroll
            for (int ql = 0; ql < 4; ql++) {
                float f = feats[(qbase + ql) * 256 + ct * 64 + c];
                acc[ql][0] = fmaf(w0, f, acc[ql][0]);
                acc[ql][1] = fmaf(w1, f, acc[ql][1]);
                acc[ql][2] = fmaf(w2, f, acc[ql][2]);
                acc[ql][3] = fmaf(w3v, f, acc[ql][3]);
            }
        }
    }
    #pragma unroll
    for (int ql = 0; ql < 4; ql++)
        #pragma unroll
        for (int j = 0; j < 4; j++)
            out[(size_t)(q0 + qbase + ql) * 128 + lane + 32 * j] = acc[ql][j] + B3f[lane + 32 * j];
}

extern "C" void kernel_launch(void* const* d_in, const int* in_sizes, int n_in,
                              void* d_out, int out_size)
{
    const float* pts  = (const float*)d_in[0];
    const float* w1a  = (const float*)d_in[1];
    const float* g1a  = (const float*)d_in[2];
    const float* bb1a = (const float*)d_in[3];
    const float* w1b  = (const float*)d_in[4];
    const float* g1b  = (const float*)d_in[5];
    const float* bb1b = (const float*)d_in[6];
    const float* w1c  = (const float*)d_in[7];
    const float* g1c  = (const float*)d_in[8];
    const float* bb1c = (const float*)d_in[9];
    const float* w2a  = (const float*)d_in[10];
    const float* g2a  = (const float*)d_in[11];
    const float* bb2a = (const float*)d_in[12];
    const float* w2b  = (const float*)d_in[13];
    const float* g2b  = (const float*)d_in[14];
    const float* bb2b = (const float*)d_in[15];
    const float* w2c  = (const float*)d_in[16];
    const float* g2c  = (const float*)d_in[17];
    const float* bb2c = (const float*)d_in[18];
    const float* w3   = (const float*)d_in[19];
    const float* b3   = (const float*)d_in[20];

    cudaFuncSetAttribute(scale_kernel, cudaFuncAttributeMaxDynamicSharedMemorySize, SMEM_TOTAL);
    cudaFuncSetAttribute(final_kernel, cudaFuncAttributeMaxDynamicSharedMemorySize, FINAL_SMEM);

    soa_kernel<<<(BATCH * NPTS + 255) / 256, 256>>>(pts);
    w3t_kernel<<<(128 * 256 + 255) / 256, 256>>>(w3);
    scale_kernel<<<2048, 256, SMEM_TOTAL>>>(w1a, g1a, bb1a, w1b, g1b, bb1b, w1c, g1c, bb1c,
                                            w2a, g2a, bb2a, w2b, g2b, bb2b, w2c, g2c, bb2c);
    final_kernel<<<NQ / 32, 256, FINAL_SMEM>>>(b3, (float*)d_out);
}